// round 17
// baseline (speedup 1.0000x reference)
#include <cuda_runtime.h>
#include <math.h>

#define B_SZ   32
#define N_TGT  50
#define OFF1   16224    // 32*3*13*13
#define OFF2   81120    // OFF1 + 32*3*26*26
#define TOTAL  340704   // OFF2 + 32*3*52*52

#define CONF_T    (TOTAL / 2)               // 170352 threads, 2 cells each
#define GRID_N    ((CONF_T + 255) / 256)    // 666 blocks
#define ENTRY_BLKS (B_SZ * 3)               // 96 blocks handle (batch, scale) corrections

// self-resetting cross-block accumulator (zero-init at load; last block
// exchanges g_sum back to 0 and clears g_done -> identical state each replay)
__device__ float        g_sum;
__device__ unsigned int g_done;

__constant__ float c_an[3][3][2] = {
    {{116.f/416.f,  90.f/416.f}, {156.f/416.f, 198.f/416.f}, {373.f/416.f, 326.f/416.f}},
    {{ 30.f/416.f,  61.f/416.f}, { 62.f/416.f,  45.f/416.f}, { 59.f/416.f, 119.f/416.f}},
    {{ 10.f/416.f,  13.f/416.f}, { 16.f/416.f,  30.f/416.f}, { 33.f/416.f,  23.f/416.f}}
};
__constant__ int   c_dim[3] = {13, 26, 52};
__constant__ int   c_off[3] = {0, OFF1, OFF2};
__constant__ float c_bal[3] = {0.4f, 1.0f, 4.0f};

__device__ __forceinline__ float softplusf(float x) {
    return fmaxf(x, 0.f) + __logf(1.f + __expf(-fabsf(x)));
}

__global__ void __launch_bounds__(256)
k_all(const float* __restrict__ pl, const float* __restrict__ pm,
      const float* __restrict__ ps, const float* __restrict__ tg,
      float* __restrict__ out) {
    __shared__ int   s_cw[N_TGT];        // win-candidate cell per target
    __shared__ int   s_sup[N_TGT * 3];   // iou>0.5 candidate cells (or -1)
    __shared__ int   s_wcell[N_TGT];     // compacted winner cells
    __shared__ int   s_wtcls[N_TGT];     // winner target class
    __shared__ int   s_cnt;
    __shared__ float s_red[8];

    int tid = threadIdx.x;
    int blk = blockIdx.x;
    int t   = blk * 256 + tid;
    float acc = 0.f;

    // ---------- dense conf loads: fully independent, issued first ----------
    float x0 = 0.f, x1 = 0.f;
    int cs = 0;
    if (t < CONF_T) {
        int c0 = t * 2;
        cs = (c0 < OFF1) ? 0 : (c0 < OFF2) ? 1 : 2;
        const float* pred = (cs == 0) ? pl : (cs == 1) ? pm : ps;
        int local0 = c0 - c_off[cs];
        x0 = __ldcg(&pred[(size_t)local0 * 85 + 4]);
        x1 = __ldcg(&pred[(size_t)local0 * 85 + 89]);
    }

    // ---------- correction work: first 96 blocks, one (batch, scale) each ----------
    if (blk < ENTRY_BLKS) {
        int b = blk / 3;
        int s = blk - b * 3;
        int W      = c_dim[s];
        int off    = c_off[s];
        int stride = W * W;
        const float* pred = (s == 0) ? pl : (s == 1) ? pm : ps;

        if (tid == 0) s_cnt = 0;

        // phase 1: per-target anchor assignment (threads 0..49)
        float rgx = 0.f, rgy = 0.f, rgw = 0.f, rgh = 0.f, rtw = 0.f, rth = 0.f;
        int   rcw = -1, rgi = 0, rgj = 0, rbn = 0, rtcls = 0;
        if (tid < N_TGT) {
            const float* row = tg + (size_t)(b * N_TGT + tid) * 5;
            rtcls = (int)__ldg(&row[0]);
            float x = __ldg(&row[1]), y = __ldg(&row[2]);
            rtw = __ldg(&row[3]);  rth = __ldg(&row[4]);
            float Wf = (float)W;
            rgx = x * Wf; rgy = y * Wf; rgw = rtw * Wf; rgh = rth * Wf;

            float ious[3];
            float best = -1.f;
            #pragma unroll
            for (int a = 0; a < 3; a++) {
                float aw = c_an[s][a][0], ah = c_an[s][a][1];
                float inter = fminf(rgw, aw) * fminf(rgh, ah);
                float iou   = inter / (rgw*rgh + aw*ah - inter + 1e-6f);
                ious[a] = iou;
                if (iou > best) { best = iou; rbn = a; }
            }
            rgi = (int)floorf(rgx);
            rgj = (int)floorf(rgy);
            int cell0 = off + ((b * 3) * W + rgj) * W + rgi;
            rcw = cell0 + rbn * stride;
            s_cw[tid] = rcw;
            #pragma unroll
            for (int a = 0; a < 3; a++)
                s_sup[tid * 3 + a] = (ious[a] > 0.5f) ? (cell0 + a * stride) : -1;
        }
        __syncthreads();

        // phase 2a: winner resolution (max-n wins); box loss + conf win correction
        if (tid < N_TGT) {
            bool win = true;
            for (int n2 = tid + 1; n2 < N_TGT; n2++)
                if (s_cw[n2] == rcw) { win = false; break; }
            if (win) {
                int idx = atomicAdd(&s_cnt, 1);
                s_wcell[idx] = rcw;
                s_wtcls[idx] = rtcls;

                int local = rcw - off;
                const float* p = pred + (size_t)local * 85;
                float conf = __ldg(&p[4]);
                acc -= 5.0f * c_bal[s] * conf;        // softplus -> softplus - conf

                float aw = c_an[s][rbn][0], ah = c_an[s][rbn][1];
                float dx  = 1.f / (1.f + __expf(-__ldg(&p[0])));
                float dy  = 1.f / (1.f + __expf(-__ldg(&p[1])));
                float b1x = dx + (float)rgi, b1y = dy + (float)rgj;
                float b1w = __expf(__ldg(&p[2])) * aw, b1h = __expf(__ldg(&p[3])) * ah;
                float b2x = rgx, b2y = rgy;
                float b2w = __expf(__logf(rgw / aw)) * aw;   // replicate ref exp(log(.))
                float b2h = __expf(__logf(rgh / ah)) * ah;

                float b1x1 = b1x - b1w*0.5f, b1x2 = b1x + b1w*0.5f;
                float b1y1 = b1y - b1h*0.5f, b1y2 = b1y + b1h*0.5f;
                float b2x1 = b2x - b2w*0.5f, b2x2 = b2x + b2w*0.5f;
                float b2y1 = b2y - b2h*0.5f, b2y2 = b2y + b2h*0.5f;

                float iw = fmaxf(fminf(b1x2, b2x2) - fmaxf(b1x1, b2x1), 0.f);
                float ih = fmaxf(fminf(b1y2, b2y2) - fmaxf(b1y1, b2y1), 0.f);
                float inter = iw * ih;
                float a1 = b1w * b1h, a2 = b2w * b2h;
                float iou = inter / (a1 + a2 - inter + 1e-6f);
                float ddx = b2x - b1x, ddy = b2y - b1y;
                float d2  = ddx*ddx + ddy*ddy;
                float cwd = fmaxf(b1x2, b2x2) - fminf(b1x1, b2x1);
                float chd = fmaxf(b1y2, b2y2) - fminf(b1y1, b2y1);
                float c2  = cwd*cwd + chd*chd + 1e-6f;
                float da  = atanf(b1w / (b1h + 1e-6f)) - atanf(b2w / (b2h + 1e-6f));
                const float four_over_pi2 = 4.0f / (3.14159265358979323846f * 3.14159265358979323846f);
                float v     = four_over_pi2 * da * da;
                float alpha = v / (1.f - iou + v + 1e-6f);
                float ciou  = iou - d2 / c2 - alpha * v;
                float bls   = 2.f - rtw * rth;
                acc += 0.05f * (1.f - ciou) * bls;
            }
        }

        // phase 2b: supp-only correction (threads 0..149), dedup + not-won check
        if (tid < N_TGT * 3) {
            int c = s_sup[tid];
            if (c >= 0) {
                bool claimed = true;
                for (int j = tid + 1; j < N_TGT * 3; j++)
                    if (s_sup[j] == c) { claimed = false; break; }
                if (claimed) {
                    bool won = false;
                    for (int n2 = 0; n2 < N_TGT; n2++)
                        if (s_cw[n2] == c) { won = true; break; }
                    if (!won) {
                        float cf = __ldcg(&pred[(size_t)(c - off) * 85 + 4]);
                        acc -= 5.0f * c_bal[s] * softplusf(cf);
                    }
                }
            }
        }
        __syncthreads();

        // phase 3: class loss over winners (nw*80 items spread over 256 threads)
        int nw = s_cnt;
        int items = nw * 80;
        for (int i = tid; i < items; i += 256) {
            int wi = i / 80;
            int k  = i - wi * 80;
            int local = s_wcell[wi] - off;
            float px  = __ldg(&pred[(size_t)local * 85 + 5 + k]);
            int tcls  = s_wtcls[wi];
            acc += softplusf(px) - ((k == tcls) ? px : 0.f);
        }
    }

    // ---------- dense conf term: 5*bal*softplus(conf) over every cell ----------
    if (t < CONF_T) {
        float e0 = 1.f + __expf(-fabsf(x0));
        float e1 = 1.f + __expf(-fabsf(x1));
        acc += 5.0f * c_bal[cs] *
               (__logf(e0 * e1) + fmaxf(x0, 0.f) + fmaxf(x1, 0.f));
    }

    // ---------- block reduction + cross-block sum ----------
    #pragma unroll
    for (int o = 16; o > 0; o >>= 1)
        acc += __shfl_down_sync(0xffffffffu, acc, o);
    int lane = tid & 31, wid = tid >> 5;
    if (lane == 0) s_red[wid] = acc;
    __syncthreads();
    if (wid == 0) {
        acc = (lane < 8) ? s_red[lane] : 0.f;
        #pragma unroll
        for (int o = 4; o > 0; o >>= 1)
            acc += __shfl_down_sync(0xffffffffu, acc, o);
        if (lane == 0) {
            atomicAdd(&g_sum, acc);
            __threadfence();
            unsigned d = atomicAdd(&g_done, 1u);
            if (d == GRID_N - 1u) {
                float tot = atomicExch(&g_sum, 0.f);   // read + reset for next replay
                g_done = 0u;
                __threadfence();
                out[0] = tot;
            }
        }
    }
}

extern "C" void kernel_launch(void* const* d_in, const int* in_sizes, int n_in,
                              void* d_out, int out_size) {
    const float* pl = (const float*)d_in[0];
    const float* pm = (const float*)d_in[1];
    const float* ps = (const float*)d_in[2];
    const float* tg = (const float*)d_in[3];
    float* out = (float*)d_out;

    k_all<<<GRID_N, 256>>>(pl, pm, ps, tg, out);
}